// round 15
// baseline (speedup 1.0000x reference)
#include <cuda_runtime.h>
#include <cuda_bf16.h>
#include <cstdint>
#include <math.h>
#include <float.h>

#define Nn 2048
#define Dd 128
#define Vv 3
#define Hh 4
#define VDd 512
#define Kk 10
#define VH (Vv*Hh)
#define LRELU_ALPHA 0.2f
#define AGG_SPLITS 16
#define AGG_KCHUNK ((VH*Dd)/AGG_SPLITS)   // 96

// ---------------- scratch (no allocations allowed) ----------------
__device__ float g_sq[Nn];
__device__ float g_dist[(size_t)Nn * Nn];
__device__ float g_f1[VH * Nn];
__device__ float g_f2[VH * Nn];
__device__ float g_part[(size_t)AGG_SPLITS * Nn * Dd];
__device__ float g_W2[(size_t)VH * Dd * Dd];

// bf16 split operands
__device__ __nv_bfloat16 g_lat_h[Nn * Dd],  g_lat_l[Nn * Dd];
__device__ __nv_bfloat16 g_gwT_h[VH * Dd * Dd], g_gwT_l[VH * Dd * Dd];
__device__ __nv_bfloat16 g_gw_h[VH * Dd * Dd],  g_gw_l[VH * Dd * Dd];
__device__ __nv_bfloat16 g_encT_h[Vv * VDd * Dd], g_encT_l[Vv * VDd * Dd];
__device__ __nv_bfloat16 g_aggT_h[Dd * VH * Dd], g_aggT_l[Dd * VH * Dd];
__device__ __nv_bfloat16 g_W2T_h[Dd * VH * Dd], g_W2T_l[Dd * VH * Dd];
__device__ __nv_bfloat16 g_clsT_h[Dd * Dd], g_clsT_l[Dd * Dd];
__device__ __nv_bfloat16 g_mix_h[(size_t)Nn * VH * Dd], g_mix_l[(size_t)Nn * VH * Dd];
__device__ __nv_bfloat16 g_sem_h[Nn * Dd], g_sem_l[Nn * Dd];

// ---------------- coalesced transpose + split (32x32 tiles) ----------------
__device__ __forceinline__ void trans_tile(
    const float* __restrict__ src, int R, int C,
    __nv_bfloat16* __restrict__ dh, __nv_bfloat16* __restrict__ dl,
    int tr, int tc, int tid)
{
    __shared__ float tile[32][33];
    int tx = tid & 31, ty = tid >> 5;
    int r0 = tr * 32, c0 = tc * 32;
    #pragma unroll
    for (int p = 0; p < 4; p++)
        tile[ty + p * 8][tx] = src[(size_t)(r0 + ty + p * 8) * C + c0 + tx];
    __syncthreads();
    #pragma unroll
    for (int p = 0; p < 4; p++) {
        int j = ty + p * 8;
        float x = tile[tx][j];
        __nv_bfloat16 h = __float2bfloat16(x);
        size_t o = (size_t)(c0 + j) * R + r0 + tx;
        dh[o] = h;
        dl[o] = __float2bfloat16(x - __bfloat162float(h));
    }
}

// combined prep: transposes (0..591), latent (592..847), gat_W plain split (848..1615)
__global__ __launch_bounds__(256) void prep_all(
    const float* __restrict__ gw, const float* __restrict__ ew,
    const float* __restrict__ aw, const float* __restrict__ cw,
    const float* __restrict__ lat)
{
    int b = blockIdx.x, tid = threadIdx.x;
    if (b < 192) {
        int z = b >> 4, t = b & 15;
        trans_tile(gw + (size_t)z * Dd * Dd, Dd, Dd,
                   g_gwT_h + (size_t)z * Dd * Dd, g_gwT_l + (size_t)z * Dd * Dd,
                   t >> 2, t & 3, tid);
    } else if (b < 384) {
        int bb = b - 192; int z = bb >> 6, t = bb & 63;
        trans_tile(ew + (size_t)z * Dd * VDd, Dd, VDd,
                   g_encT_h + (size_t)z * VDd * Dd, g_encT_l + (size_t)z * VDd * Dd,
                   t >> 4, t & 15, tid);
    } else if (b < 576) {
        int t = b - 384;
        trans_tile(aw, VH * Dd, Dd, g_aggT_h, g_aggT_l, t >> 2, t & 3, tid);
    } else if (b < 592) {
        int t = b - 576;
        trans_tile(cw, Dd, Dd, g_clsT_h, g_clsT_l, t >> 2, t & 3, tid);
    } else if (b < 848) {
        int w = (b - 592) * 8 + (tid >> 5);
        int lane = tid & 31;
        float4 r = *(const float4*)(lat + (size_t)w * Dd + lane * 4);
        union { __nv_bfloat16 bb[4]; uint2 u; } H, L;
        float c[4] = {r.x, r.y, r.z, r.w};
        #pragma unroll
        for (int q = 0; q < 4; q++) {
            H.bb[q] = __float2bfloat16(c[q]);
            L.bb[q] = __float2bfloat16(c[q] - __bfloat162float(H.bb[q]));
        }
        *(uint2*)(g_lat_h + (size_t)w * Dd + lane * 4) = H.u;
        *(uint2*)(g_lat_l + (size_t)w * Dd + lane * 4) = L.u;
        float s = c[0]*c[0] + c[1]*c[1] + c[2]*c[2] + c[3]*c[3];
        #pragma unroll
        for (int o = 16; o; o >>= 1) s += __shfl_xor_sync(0xffffffffu, s, o);
        if (lane == 0) g_sq[w] = s;
    } else {
        int i = (b - 848) * 256 + tid;
        float x = gw[i];
        __nv_bfloat16 h = __float2bfloat16(x);
        g_gw_h[i] = h;
        g_gw_l[i] = __float2bfloat16(x - __bfloat162float(h));
    }
}

#define MMA_BF16(c, a0, a1, a2, a3, b0, b1) \
    asm volatile("mma.sync.aligned.m16n8k16.row.col.f32.bf16.bf16.f32 " \
                 "{%0,%1,%2,%3}, {%4,%5,%6,%7}, {%8,%9}, {%0,%1,%2,%3};" \
                 : "+f"((c)[0]), "+f"((c)[1]), "+f"((c)[2]), "+f"((c)[3]) \
                 : "r"(a0), "r"(a1), "r"(a2), "r"(a3), "r"(b0), "r"(b1))

struct BmmaSmem {
    __nv_bfloat16 Ash[128][40];
    __nv_bfloat16 Asl[128][40];
    __nv_bfloat16 Bsh[128][40];
    __nv_bfloat16 Bsl[128][40];
    float red1[4][128];
    float red2[4][128];
    float srow[128];
};

// =====================================================================
// bf16 split-compensated tensor-core GEMM tile (device fn).
// MODE: 0 plain, 1 +bias[col], 3 dist epilogue,
//       4 f1/f2 row-dots ONLY (no C store; biasb = gat_a[z], bn==0),
//       5 +biasb, elu, row log_softmax fused (bn==0, writes final output)
// =====================================================================
template <int MODE>
__device__ __forceinline__ void bmma_tile(
    BmmaSmem* sm,
    const __nv_bfloat16* __restrict__ Ahb, const __nv_bfloat16* __restrict__ Alb,
    const __nv_bfloat16* __restrict__ Bhb, const __nv_bfloat16* __restrict__ Blb,
    float* __restrict__ Cb, const float* __restrict__ bias,
    const float* __restrict__ biasb,
    int z, int bm, int bn, int Kdim, int lda, int ldb, int ldc)
{
    const int tid = threadIdx.x;
    const int wid = tid >> 5, lane = tid & 31;
    const int wm = wid >> 2, wn = wid & 3;
    const int gr = lane >> 2, ct = lane & 3;
    const int r0 = tid >> 2;
    const int cv = (tid & 3) * 8;

    float acc[4][4][4];
    #pragma unroll
    for (int mt = 0; mt < 4; mt++)
        #pragma unroll
        for (int nt = 0; nt < 4; nt++)
            #pragma unroll
            for (int q = 0; q < 4; q++) acc[mt][nt][q] = 0.f;

    const int T = Kdim >> 5;
    for (int t = 0; t < T; t++) {
        const int k0 = t * 32;
        uint4 gah0 = *(const uint4*)(Ahb + (size_t)(bm + r0) * lda + k0 + cv);
        uint4 gah1 = *(const uint4*)(Ahb + (size_t)(bm + r0 + 64) * lda + k0 + cv);
        uint4 gal0 = *(const uint4*)(Alb + (size_t)(bm + r0) * lda + k0 + cv);
        uint4 gal1 = *(const uint4*)(Alb + (size_t)(bm + r0 + 64) * lda + k0 + cv);
        uint4 gbh0 = *(const uint4*)(Bhb + (size_t)(bn + r0) * ldb + k0 + cv);
        uint4 gbh1 = *(const uint4*)(Bhb + (size_t)(bn + r0 + 64) * ldb + k0 + cv);
        uint4 gbl0 = *(const uint4*)(Blb + (size_t)(bn + r0) * ldb + k0 + cv);
        uint4 gbl1 = *(const uint4*)(Blb + (size_t)(bn + r0 + 64) * ldb + k0 + cv);

        __syncthreads();
        *(uint4*)&sm->Ash[r0][cv] = gah0;  *(uint4*)&sm->Ash[r0 + 64][cv] = gah1;
        *(uint4*)&sm->Asl[r0][cv] = gal0;  *(uint4*)&sm->Asl[r0 + 64][cv] = gal1;
        *(uint4*)&sm->Bsh[r0][cv] = gbh0;  *(uint4*)&sm->Bsh[r0 + 64][cv] = gbh1;
        *(uint4*)&sm->Bsl[r0][cv] = gbl0;  *(uint4*)&sm->Bsl[r0 + 64][cv] = gbl1;
        __syncthreads();

        #pragma unroll
        for (int kk = 0; kk < 32; kk += 16) {
            uint32_t bh[4][2], bl[4][2];
            #pragma unroll
            for (int nt = 0; nt < 4; nt++) {
                int n = wn * 32 + nt * 8 + gr;
                bh[nt][0] = *(const uint32_t*)&sm->Bsh[n][kk + ct * 2];
                bh[nt][1] = *(const uint32_t*)&sm->Bsh[n][kk + ct * 2 + 8];
                bl[nt][0] = *(const uint32_t*)&sm->Bsl[n][kk + ct * 2];
                bl[nt][1] = *(const uint32_t*)&sm->Bsl[n][kk + ct * 2 + 8];
            }
            #pragma unroll
            for (int mt = 0; mt < 4; mt++) {
                int rA = wm * 64 + mt * 16 + gr;
                uint32_t ah0 = *(const uint32_t*)&sm->Ash[rA][kk + ct * 2];
                uint32_t ah1 = *(const uint32_t*)&sm->Ash[rA + 8][kk + ct * 2];
                uint32_t ah2 = *(const uint32_t*)&sm->Ash[rA][kk + ct * 2 + 8];
                uint32_t ah3 = *(const uint32_t*)&sm->Ash[rA + 8][kk + ct * 2 + 8];
                uint32_t al0 = *(const uint32_t*)&sm->Asl[rA][kk + ct * 2];
                uint32_t al1 = *(const uint32_t*)&sm->Asl[rA + 8][kk + ct * 2];
                uint32_t al2 = *(const uint32_t*)&sm->Asl[rA][kk + ct * 2 + 8];
                uint32_t al3 = *(const uint32_t*)&sm->Asl[rA + 8][kk + ct * 2 + 8];
                #pragma unroll
                for (int nt = 0; nt < 4; nt++) {
                    MMA_BF16(acc[mt][nt], ah0, ah1, ah2, ah3, bh[nt][0], bh[nt][1]);
                    MMA_BF16(acc[mt][nt], ah0, ah1, ah2, ah3, bl[nt][0], bl[nt][1]);
                    MMA_BF16(acc[mt][nt], al0, al1, al2, al3, bh[nt][0], bh[nt][1]);
                }
            }
        }
    }

    if (MODE != 5 && MODE != 4) {
        #pragma unroll
        for (int mt = 0; mt < 4; mt++) {
            int row = bm + wm * 64 + mt * 16 + gr;
            #pragma unroll
            for (int nt = 0; nt < 4; nt++) {
                int col = bn + wn * 32 + nt * 8 + ct * 2;
                float v0 = acc[mt][nt][0], v1 = acc[mt][nt][1];
                float v2 = acc[mt][nt][2], v3 = acc[mt][nt][3];
                if (MODE == 1) {
                    float b0 = biasb[col], b1 = biasb[col + 1];
                    v0 += b0; v1 += b1; v2 += b0; v3 += b1;
                } else if (MODE == 3) {
                    float sr0 = bias[row], sr1 = bias[row + 8];
                    float sc0 = bias[col], sc1 = bias[col + 1];
                    v0 = sr0 + sc0 - 2.f * v0;
                    v1 = sr0 + sc1 - 2.f * v1;
                    v2 = sr1 + sc0 - 2.f * v2;
                    v3 = sr1 + sc1 - 2.f * v3;
                }
                *(float2*)(Cb + (size_t)row * ldc + col) = make_float2(v0, v1);
                *(float2*)(Cb + (size_t)(row + 8) * ldc + col) = make_float2(v2, v3);
            }
        }
    }

    if (MODE == 4) {
        float a1c[4][2], a2c[4][2];
        #pragma unroll
        for (int nt = 0; nt < 4; nt++) {
            int col = wn * 32 + nt * 8 + ct * 2;
            a1c[nt][0] = biasb[col];      a1c[nt][1] = biasb[col + 1];
            a2c[nt][0] = biasb[Dd + col]; a2c[nt][1] = biasb[Dd + col + 1];
        }
        float p1[8], p2[8];
        #pragma unroll
        for (int ri = 0; ri < 8; ri++) {
            int mt = ri >> 1, h2 = ri & 1;
            float s1 = 0.f, s2 = 0.f;
            #pragma unroll
            for (int nt = 0; nt < 4; nt++) {
                float v0 = acc[mt][nt][h2 * 2 + 0], v1 = acc[mt][nt][h2 * 2 + 1];
                s1 += v0 * a1c[nt][0] + v1 * a1c[nt][1];
                s2 += v0 * a2c[nt][0] + v1 * a2c[nt][1];
            }
            p1[ri] = s1; p2[ri] = s2;
        }
        #pragma unroll
        for (int ri = 0; ri < 8; ri++) {
            p1[ri] += __shfl_xor_sync(0xffffffffu, p1[ri], 1);
            p1[ri] += __shfl_xor_sync(0xffffffffu, p1[ri], 2);
            p2[ri] += __shfl_xor_sync(0xffffffffu, p2[ri], 1);
            p2[ri] += __shfl_xor_sync(0xffffffffu, p2[ri], 2);
        }
        if (ct == 0) {
            #pragma unroll
            for (int ri = 0; ri < 8; ri++) {
                int rl = wm * 64 + (ri >> 1) * 16 + gr + (ri & 1) * 8;
                sm->red1[wn][rl] = p1[ri];
                sm->red2[wn][rl] = p2[ri];
            }
        }
        __syncthreads();
        if (tid < 128) {
            float f1 = sm->red1[0][tid] + sm->red1[1][tid] + sm->red1[2][tid] + sm->red1[3][tid];
            float f2 = sm->red2[0][tid] + sm->red2[1][tid] + sm->red2[2][tid] + sm->red2[3][tid];
            g_f1[(size_t)z * Nn + bm + tid] = f1;
            g_f2[(size_t)z * Nn + bm + tid] = f2;
        }
    }

    if (MODE == 5) {
        #pragma unroll
        for (int mt = 0; mt < 4; mt++)
            #pragma unroll
            for (int nt = 0; nt < 4; nt++) {
                int col = wn * 32 + nt * 8 + ct * 2;
                float b0 = biasb[col], b1 = biasb[col + 1];
                acc[mt][nt][0] += b0; acc[mt][nt][1] += b1;
                acc[mt][nt][2] += b0; acc[mt][nt][3] += b1;
                #pragma unroll
                for (int q = 0; q < 4; q++) {
                    float v = acc[mt][nt][q];
                    acc[mt][nt][q] = (v > 0.f) ? v : expm1f(v);
                }
            }
        float rm[8];
        #pragma unroll
        for (int ri = 0; ri < 8; ri++) {
            int mt = ri >> 1, h2 = ri & 1;
            float m = -FLT_MAX;
            #pragma unroll
            for (int nt = 0; nt < 4; nt++)
                m = fmaxf(m, fmaxf(acc[mt][nt][h2 * 2], acc[mt][nt][h2 * 2 + 1]));
            rm[ri] = m;
        }
        #pragma unroll
        for (int ri = 0; ri < 8; ri++) {
            rm[ri] = fmaxf(rm[ri], __shfl_xor_sync(0xffffffffu, rm[ri], 1));
            rm[ri] = fmaxf(rm[ri], __shfl_xor_sync(0xffffffffu, rm[ri], 2));
        }
        if (ct == 0)
            #pragma unroll
            for (int ri = 0; ri < 8; ri++)
                sm->red1[wn][wm * 64 + (ri >> 1) * 16 + gr + (ri & 1) * 8] = rm[ri];
        __syncthreads();
        if (tid < 128)
            sm->srow[tid] = fmaxf(fmaxf(sm->red1[0][tid], sm->red1[1][tid]),
                                  fmaxf(sm->red1[2][tid], sm->red1[3][tid]));
        __syncthreads();
        float se[8];
        #pragma unroll
        for (int ri = 0; ri < 8; ri++) {
            int mt = ri >> 1, h2 = ri & 1;
            int rl = wm * 64 + mt * 16 + gr + h2 * 8;
            float m = sm->srow[rl];
            float s = 0.f;
            #pragma unroll
            for (int nt = 0; nt < 4; nt++)
                s += expf(acc[mt][nt][h2 * 2] - m) + expf(acc[mt][nt][h2 * 2 + 1] - m);
            se[ri] = s;
        }
        #pragma unroll
        for (int ri = 0; ri < 8; ri++) {
            se[ri] += __shfl_xor_sync(0xffffffffu, se[ri], 1);
            se[ri] += __shfl_xor_sync(0xffffffffu, se[ri], 2);
        }
        __syncthreads();
        if (ct == 0)
            #pragma unroll
            for (int ri = 0; ri < 8; ri++)
                sm->red1[wn][wm * 64 + (ri >> 1) * 16 + gr + (ri & 1) * 8] = se[ri];
        __syncthreads();
        if (tid < 128)
            sm->srow[tid] += logf(sm->red1[0][tid] + sm->red1[1][tid] +
                                  sm->red1[2][tid] + sm->red1[3][tid]);
        __syncthreads();
        #pragma unroll
        for (int mt = 0; mt < 4; mt++) {
            #pragma unroll
            for (int nt = 0; nt < 4; nt++) {
                int col = wn * 32 + nt * 8 + ct * 2;
                int rl0 = wm * 64 + mt * 16 + gr;
                float l0 = sm->srow[rl0], l1 = sm->srow[rl0 + 8];
                *(float2*)(Cb + (size_t)(bm + rl0) * ldc + col) =
                    make_float2(acc[mt][nt][0] - l0, acc[mt][nt][1] - l0);
                *(float2*)(Cb + (size_t)(bm + rl0 + 8) * ldc + col) =
                    make_float2(acc[mt][nt][2] - l1, acc[mt][nt][3] - l1);
            }
        }
    }
}

// ---- mega GEMM: dist (0..255) + f12 (256..447) + rec (448..639) + W2 (640..651) ----
__global__ __launch_bounds__(256, 2) void mega_gemm(
    float* __restrict__ rec, const float* __restrict__ gat_a,
    const float* __restrict__ enc_b)
{
    __shared__ BmmaSmem sm;
    int b = blockIdx.x;
    if (b < 256) {
        bmma_tile<3>(&sm, g_lat_h, g_lat_l, g_lat_h, g_lat_l,
                     g_dist, g_sq, nullptr,
                     0, (b >> 4) * 128, (b & 15) * 128, Dd, Dd, Dd, Nn);
    } else if (b < 448) {
        int t = b - 256; int z = t >> 4; int bm = (t & 15) * 128;
        bmma_tile<4>(&sm, g_lat_h, g_lat_l,
                     g_gwT_h + (size_t)z * Dd * Dd, g_gwT_l + (size_t)z * Dd * Dd,
                     nullptr, nullptr, gat_a + (size_t)z * 2 * Dd,
                     z, bm, 0, Dd, Dd, Dd, Dd);
    } else if (b < 640) {
        int t = b - 448; int z = t >> 6; int r = t & 63;
        bmma_tile<1>(&sm, g_lat_h, g_lat_l,
                     g_encT_h + (size_t)z * VDd * Dd, g_encT_l + (size_t)z * VDd * Dd,
                     rec + (size_t)z * Nn * VDd, nullptr, enc_b + (size_t)z * VDd,
                     z, (r >> 2) * 128, (r & 3) * 128, Dd, Dd, Dd, VDd);
    } else {
        int vh = b - 640;
        bmma_tile<0>(&sm,
                     g_gw_h + (size_t)vh * Dd * Dd, g_gw_l + (size_t)vh * Dd * Dd,
                     g_aggT_h + (size_t)vh * Dd, g_aggT_l + (size_t)vh * Dd,
                     g_W2 + (size_t)vh * Dd * Dd, nullptr, nullptr,
                     vh, 0, 0, Dd, Dd, VH * Dd, Dd);
    }
}

// ---------------- semantic partials = mixed @ W2 (split-K 16) ----------------
__global__ __launch_bounds__(256, 2) void agg_gemm() {
    __shared__ BmmaSmem sm;
    int z = blockIdx.z;
    bmma_tile<0>(&sm,
                 g_mix_h + (size_t)z * AGG_KCHUNK, g_mix_l + (size_t)z * AGG_KCHUNK,
                 g_W2T_h + (size_t)z * AGG_KCHUNK, g_W2T_l + (size_t)z * AGG_KCHUNK,
                 g_part + (size_t)z * Nn * Dd, nullptr, nullptr,
                 z, blockIdx.y * 128, 0, AGG_KCHUNK, VH * Dd, VH * Dd, Dd);
}

// ---------------- cls + elu + log_softmax (final output) ----------------
__global__ __launch_bounds__(256) void cls_gemm(float* __restrict__ outp,
                                                const float* __restrict__ cls_b) {
    __shared__ BmmaSmem sm;
    bmma_tile<5>(&sm, g_sem_h, g_sem_l, g_clsT_h, g_clsT_l,
                 outp, nullptr, cls_b,
                 0, blockIdx.y * 128, 0, Dd, Dd, Dd, Dd);
}

// ---- fused knn + attn (blocks 0..1023) + W2 transpose/split (1024..1215) ----
__global__ __launch_bounds__(256) void knn_attn_kernel(const float* __restrict__ fm,
                                                       const float* __restrict__ latent) {
    if (blockIdx.x >= Nn / 2) {
        int t = blockIdx.x - Nn / 2;
        trans_tile(g_W2, VH * Dd, Dd, g_W2T_h, g_W2T_l, t >> 2, t & 3, threadIdx.x);
        return;
    }
    __shared__ float sval[8][Kk];
    __shared__ int   sidx[8][Kk];
    __shared__ int   sknn[2][Kk];
    int tid = threadIdx.x;
    int wid = tid >> 5, lane = tid & 31;
    int row = blockIdx.x * 2 + (wid >> 2);
    int quarter = wid & 3;
    const float* dr = g_dist + (size_t)row * Nn + quarter * 512;

    float4 v4[4];
    #pragma unroll
    for (int t = 0; t < 4; t++)
        v4[t] = *(const float4*)(dr + t * 128 + lane * 4);

    float val[Kk];
    int   idx[Kk];
    #pragma unroll
    for (int p = 0; p < Kk; p++) { val[p] = FLT_MAX; idx[p] = 0x7fffffff; }

    #pragma unroll
    for (int t = 0; t < 4; t++) {
        float c[4] = {v4[t].x, v4[t].y, v4[t].z, v4[t].w};
        #pragma unroll
        for (int q = 0; q < 4; q++) {
            float d = c[q];
            if (d < val[Kk - 1]) {
                int gj = quarter * 512 + t * 128 + lane * 4 + q;
                #pragma unroll
                for (int p = Kk - 1; p >= 1; p--) {
                    if (d < val[p]) {
                        bool sh = d < val[p - 1];
                        val[p] = sh ? val[p - 1] : d;
                        idx[p] = sh ? idx[p - 1] : gj;
                    }
                }
                if (d < val[0]) { val[0] = d; idx[0] = gj; }
            }
        }
    }

    #pragma unroll 1
    for (int r = 0; r < Kk; r++) {
        float bv = val[0]; int bi = idx[0];
        #pragma unroll
        for (int o = 16; o; o >>= 1) {
            float ov = __shfl_xor_sync(0xffffffffu, bv, o);
            int   oi = __shfl_xor_sync(0xffffffffu, bi, o);
            if (ov < bv || (ov == bv && oi < bi)) { bv = ov; bi = oi; }
        }
        if (lane == 0) { sval[wid][r] = bv; sidx[wid][r] = bi; }
        if (val[0] == bv && idx[0] == bi) {
            #pragma unroll
            for (int p = 0; p < Kk - 1; p++) { val[p] = val[p + 1]; idx[p] = idx[p + 1]; }
            val[Kk - 1] = FLT_MAX; idx[Kk - 1] = 0x7fffffff;
        }
    }
    __syncthreads();

    if ((wid & 3) == 0) {
        int wbase = wid;
        float a = FLT_MAX; int ai = 0x7fffffff;
        float b = FLT_MAX; int bi = 0x7fffffff;
        if (lane < 40) { a = sval[wbase + lane / Kk][lane % Kk]; ai = sidx[wbase + lane / Kk][lane % Kk]; }
        int l2 = lane + 32;
        if (l2 < 40) { b = sval[wbase + l2 / Kk][l2 % Kk]; bi = sidx[wbase + l2 / Kk][l2 % Kk]; }
        #pragma unroll 1
        for (int r = 0; r < Kk; r++) {
            bool useB = (b < a) || (b == a && bi < ai);
            float cv = useB ? b : a;
            int   ci = useB ? bi : ai;
            float mv = cv; int mi = ci;
            #pragma unroll
            for (int o = 16; o; o >>= 1) {
                float ov = __shfl_xor_sync(0xffffffffu, mv, o);
                int   oi = __shfl_xor_sync(0xffffffffu, mi, o);
                if (ov < mv || (ov == mv && oi < mi)) { mv = ov; mi = oi; }
            }
            if (lane == 0) sknn[wid >> 2][r] = mi;
            if (cv == mv && ci == mi) {
                if (useB) { b = FLT_MAX; bi = 0x7fffffff; }
                else      { a = FLT_MAX; ai = 0x7fffffff; }
            }
        }
    }
    __syncthreads();

    // ---- attention phase: 24 tasks (2 rows x 12 vh), 3 per warp ----
    #pragma unroll 1
    for (int tt = wid; tt < 2 * VH; tt += 8) {
        int rl = tt / VH;
        int vh = tt - rl * VH;
        int i = blockIdx.x * 2 + rl;
        int v = vh >> 2;

        int nb = -1;
        bool valid = false;
        if (lane < Kk) {
            nb = sknn[rl][lane];
            valid = (nb == i) || (fm[(size_t)i * Vv + v] > 0.f && fm[(size_t)nb * Vv + v] > 0.f);
        }
        unsigned hasSelf = __ballot_sync(0xffffffffu, lane < Kk && nb == i);
        if (hasSelf == 0 && lane == Kk) { nb = i; valid = true; }

        float e = -FLT_MAX;
        if (valid) {
            float x = g_f1[vh * Nn + i] + g_f2[(size_t)vh * Nn + nb];
            e = (x >= 0.f) ? x : LRELU_ALPHA * x;
        }
        float m = e;
        #pragma unroll
        for (int o = 16; o; o >>= 1) m = fmaxf(m, __shfl_xor_sync(0xffffffffu, m, o));
        float wt = valid ? expf(e - m) : 0.f;
        float s = wt;
        #pragma unroll
        for (int o = 16; o; o >>= 1) s += __shfl_xor_sync(0xffffffffu, s, o);
        float att = wt / s;

        float av[Kk + 1];
        int   nj[Kk + 1];
        #pragma unroll
        for (int j = 0; j <= Kk; j++) {
            av[j] = __shfl_sync(0xffffffffu, att, j);
            int n = __shfl_sync(0xffffffffu, nb, j);
            nj[j] = (av[j] != 0.f) ? n : i;
        }
        float4 wv[Kk + 1];
        #pragma unroll
        for (int j = 0; j <= Kk; j++)
            wv[j] = *(const float4*)(latent + (size_t)nj[j] * Dd + lane * 4);

        float acc0 = 0.f, acc1 = 0.f, acc2 = 0.f, acc3 = 0.f;
        #pragma unroll
        for (int j = 0; j <= Kk; j++) {
            acc0 = fmaf(av[j], wv[j].x, acc0);
            acc1 = fmaf(av[j], wv[j].y, acc1);
            acc2 = fmaf(av[j], wv[j].z, acc2);
            acc3 = fmaf(av[j], wv[j].w, acc3);
        }
        union { __nv_bfloat16 b[4]; uint2 u; } H, L;
        float c4[4] = {acc0, acc1, acc2, acc3};
        #pragma unroll
        for (int q = 0; q < 4; q++) {
            H.b[q] = __float2bfloat16(c4[q]);
            L.b[q] = __float2bfloat16(c4[q] - __bfloat162float(H.b[q]));
        }
        size_t dst = (size_t)i * (VH * Dd) + (size_t)vh * Dd + lane * 4;
        *(uint2*)(g_mix_h + dst) = H.u;
        *(uint2*)(g_mix_l + dst) = L.u;
    }
}

// ---------------- split-K reduce for semantic + bias -> sem fp32 + bf16 split ----------------
__global__ void agg_reduce_kernel(const float* __restrict__ bias, float* __restrict__ sem) {
    int i = blockIdx.x * blockDim.x + threadIdx.x;
    if (i >= Nn * Dd) return;
    float s = 0.f;
    #pragma unroll
    for (int p = 0; p < AGG_SPLITS; p++) s += g_part[(size_t)p * Nn * Dd + i];
    s += bias[i & (Dd - 1)];
    sem[i] = s;
    __nv_bfloat16 h = __float2bfloat16(s);
    g_sem_h[i] = h;
    g_sem_l[i] = __float2bfloat16(s - __bfloat162float(h));
}

// ---------------- launch ----------------
extern "C" void kernel_launch(void* const* d_in, const int* in_sizes, int n_in,
                              void* d_out, int out_size) {
    const float* fm     = (const float*)d_in[0];
    const float* latent = (const float*)d_in[1];
    const float* enc_W  = (const float*)d_in[2];
    const float* enc_b  = (const float*)d_in[3];
    const float* gat_W  = (const float*)d_in[4];
    const float* gat_a  = (const float*)d_in[5];
    const float* agg_W  = (const float*)d_in[6];
    const float* agg_b  = (const float*)d_in[7];
    const float* cls_W  = (const float*)d_in[8];
    const float* cls_b  = (const float*)d_in[9];

    float* out  = (float*)d_out;
    float* rec  = out;                                   // [V,N,VD]
    float* outp = out + (size_t)Vv * Nn * VDd;           // [N,D]
    float* sem  = outp + (size_t)Nn * Dd;                // [N,D]

    // 1. prep: transposes/splits + latent + plain gat_W split
    prep_all<<<1616, 256>>>(gat_W, enc_W, agg_W, cls_W, latent);
    // 2. mega GEMM: dist + f12 + rec + W2
    mega_gemm<<<652, 256>>>(rec, gat_a, enc_b);
    // 3. fused knn + attention (smem knn handoff) + W2 transpose
    knn_attn_kernel<<<Nn / 2 + 192, 256>>>(fm, latent);
    // 4. semantic partials = mixed @ W2 (split-K 16)
    agg_gemm<<<dim3(1, Nn / 128, AGG_SPLITS), 256>>>();
    // 5. reduce partials + bias -> semantic (fp32 out + bf16 split)
    agg_reduce_kernel<<<(Nn * Dd) / 256, 256>>>(agg_b, sem);
    // 6. output = log_softmax(elu(sem @ cls_W + cls_b))
    cls_gemm<<<dim3(1, Nn / 128, 1), 256>>>(outp, cls_b);
}

// round 16
// speedup vs baseline: 1.0534x; 1.0534x over previous
#include <cuda_runtime.h>
#include <cuda_bf16.h>
#include <cstdint>
#include <math.h>
#include <float.h>

#define Nn 2048
#define Dd 128
#define Vv 3
#define Hh 4
#define VDd 512
#define Kk 10
#define VH (Vv*Hh)
#define LRELU_ALPHA 0.2f
#define AGG_SPLITS 8
#define AGG_KCHUNK ((VH*Dd)/AGG_SPLITS)   // 192

// ---------------- scratch (no allocations allowed) ----------------
__device__ float g_sq[Nn];
__device__ float g_dist[(size_t)Nn * Nn];
__device__ float g_f1[VH * Nn];
__device__ float g_f2[VH * Nn];
__device__ float g_part[(size_t)AGG_SPLITS * Nn * Dd];
__device__ float g_W2[(size_t)VH * Dd * Dd];

// bf16 split operands
__device__ __nv_bfloat16 g_lat_h[Nn * Dd],  g_lat_l[Nn * Dd];
__device__ __nv_bfloat16 g_gwT_h[VH * Dd * Dd], g_gwT_l[VH * Dd * Dd];
__device__ __nv_bfloat16 g_gw_h[VH * Dd * Dd],  g_gw_l[VH * Dd * Dd];
__device__ __nv_bfloat16 g_encT_h[Vv * VDd * Dd], g_encT_l[Vv * VDd * Dd];
__device__ __nv_bfloat16 g_aggT_h[Dd * VH * Dd], g_aggT_l[Dd * VH * Dd];
__device__ __nv_bfloat16 g_W2T_h[Dd * VH * Dd], g_W2T_l[Dd * VH * Dd];
__device__ __nv_bfloat16 g_clsT_h[Dd * Dd], g_clsT_l[Dd * Dd];
__device__ __nv_bfloat16 g_mix_h[(size_t)Nn * VH * Dd], g_mix_l[(size_t)Nn * VH * Dd];
__device__ __nv_bfloat16 g_sem_h[Nn * Dd], g_sem_l[Nn * Dd];

// ---------------- coalesced transpose + split (32x32 tiles) ----------------
__device__ __forceinline__ void trans_tile(
    const float* __restrict__ src, int R, int C,
    __nv_bfloat16* __restrict__ dh, __nv_bfloat16* __restrict__ dl,
    int tr, int tc, int tid)
{
    __shared__ float tile[32][33];
    int tx = tid & 31, ty = tid >> 5;
    int r0 = tr * 32, c0 = tc * 32;
    #pragma unroll
    for (int p = 0; p < 4; p++)
        tile[ty + p * 8][tx] = src[(size_t)(r0 + ty + p * 8) * C + c0 + tx];
    __syncthreads();
    #pragma unroll
    for (int p = 0; p < 4; p++) {
        int j = ty + p * 8;
        float x = tile[tx][j];
        __nv_bfloat16 h = __float2bfloat16(x);
        size_t o = (size_t)(c0 + j) * R + r0 + tx;
        dh[o] = h;
        dl[o] = __float2bfloat16(x - __bfloat162float(h));
    }
}

// combined prep: transposes (0..591), latent (592..847), gat_W plain split (848..1615)
__global__ __launch_bounds__(256) void prep_all(
    const float* __restrict__ gw, const float* __restrict__ ew,
    const float* __restrict__ aw, const float* __restrict__ cw,
    const float* __restrict__ lat)
{
    int b = blockIdx.x, tid = threadIdx.x;
    if (b < 192) {
        int z = b >> 4, t = b & 15;
        trans_tile(gw + (size_t)z * Dd * Dd, Dd, Dd,
                   g_gwT_h + (size_t)z * Dd * Dd, g_gwT_l + (size_t)z * Dd * Dd,
                   t >> 2, t & 3, tid);
    } else if (b < 384) {
        int bb = b - 192; int z = bb >> 6, t = bb & 63;
        trans_tile(ew + (size_t)z * Dd * VDd, Dd, VDd,
                   g_encT_h + (size_t)z * VDd * Dd, g_encT_l + (size_t)z * VDd * Dd,
                   t >> 4, t & 15, tid);
    } else if (b < 576) {
        int t = b - 384;
        trans_tile(aw, VH * Dd, Dd, g_aggT_h, g_aggT_l, t >> 2, t & 3, tid);
    } else if (b < 592) {
        int t = b - 576;
        trans_tile(cw, Dd, Dd, g_clsT_h, g_clsT_l, t >> 2, t & 3, tid);
    } else if (b < 848) {
        int w = (b - 592) * 8 + (tid >> 5);
        int lane = tid & 31;
        float4 r = *(const float4*)(lat + (size_t)w * Dd + lane * 4);
        union { __nv_bfloat16 bb[4]; uint2 u; } H, L;
        float c[4] = {r.x, r.y, r.z, r.w};
        #pragma unroll
        for (int q = 0; q < 4; q++) {
            H.bb[q] = __float2bfloat16(c[q]);
            L.bb[q] = __float2bfloat16(c[q] - __bfloat162float(H.bb[q]));
        }
        *(uint2*)(g_lat_h + (size_t)w * Dd + lane * 4) = H.u;
        *(uint2*)(g_lat_l + (size_t)w * Dd + lane * 4) = L.u;
        float s = c[0]*c[0] + c[1]*c[1] + c[2]*c[2] + c[3]*c[3];
        #pragma unroll
        for (int o = 16; o; o >>= 1) s += __shfl_xor_sync(0xffffffffu, s, o);
        if (lane == 0) g_sq[w] = s;
    } else {
        int i = (b - 848) * 256 + tid;
        float x = gw[i];
        __nv_bfloat16 h = __float2bfloat16(x);
        g_gw_h[i] = h;
        g_gw_l[i] = __float2bfloat16(x - __bfloat162float(h));
    }
}

#define MMA_BF16(c, a0, a1, a2, a3, b0, b1) \
    asm volatile("mma.sync.aligned.m16n8k16.row.col.f32.bf16.bf16.f32 " \
                 "{%0,%1,%2,%3}, {%4,%5,%6,%7}, {%8,%9}, {%0,%1,%2,%3};" \
                 : "+f"((c)[0]), "+f"((c)[1]), "+f"((c)[2]), "+f"((c)[3]) \
                 : "r"(a0), "r"(a1), "r"(a2), "r"(a3), "r"(b0), "r"(b1))

__device__ __forceinline__ void cpa16(void* smem, const void* gmem) {
    uint32_t s = (uint32_t)__cvta_generic_to_shared(smem);
    asm volatile("cp.async.cg.shared.global [%0], [%1], 16;\n" :: "r"(s), "l"(gmem));
}
#define CPA_COMMIT() asm volatile("cp.async.commit_group;\n")
#define CPA_WAIT(n)  asm volatile("cp.async.wait_group %0;\n" :: "n"(n))

struct BmmaStage {
    __nv_bfloat16 Ash[128][40];
    __nv_bfloat16 Asl[128][40];
    __nv_bfloat16 Bsh[128][40];
    __nv_bfloat16 Bsl[128][40];
};
struct BmmaSmem {
    BmmaStage st[2];
    float red1[4][128];
    float red2[4][128];
    float srow[128];
};
#define BMMA_SMEM_BYTES sizeof(BmmaSmem)

// =====================================================================
// bf16 split-compensated tensor-core GEMM tile, cp.async double-buffered.
// MODE: 0 plain, 1 +bias[col], 3 dist epilogue,
//       4 f1/f2 row-dots ONLY (no C store; biasb = gat_a[z], bn==0),
//       5 +biasb, elu, row log_softmax fused (bn==0, writes final output)
// =====================================================================
template <int MODE>
__device__ __forceinline__ void bmma_tile(
    BmmaSmem* sm,
    const __nv_bfloat16* __restrict__ Ahb, const __nv_bfloat16* __restrict__ Alb,
    const __nv_bfloat16* __restrict__ Bhb, const __nv_bfloat16* __restrict__ Blb,
    float* __restrict__ Cb, const float* __restrict__ bias,
    const float* __restrict__ biasb,
    int z, int bm, int bn, int Kdim, int lda, int ldb, int ldc)
{
    const int tid = threadIdx.x;
    const int wid = tid >> 5, lane = tid & 31;
    const int wm = wid >> 2, wn = wid & 3;
    const int gr = lane >> 2, ct = lane & 3;
    const int r0 = tid >> 2;
    const int cv = (tid & 3) * 8;

    float acc[4][4][4];
    #pragma unroll
    for (int mt = 0; mt < 4; mt++)
        #pragma unroll
        for (int nt = 0; nt < 4; nt++)
            #pragma unroll
            for (int q = 0; q < 4; q++) acc[mt][nt][q] = 0.f;

    const int T = Kdim >> 5;

    // stage loader via cp.async (8 x 16B per thread)
    auto load_stage = [&](BmmaStage* st, int k0) {
        cpa16(&st->Ash[r0][cv],      Ahb + (size_t)(bm + r0) * lda + k0 + cv);
        cpa16(&st->Ash[r0 + 64][cv], Ahb + (size_t)(bm + r0 + 64) * lda + k0 + cv);
        cpa16(&st->Asl[r0][cv],      Alb + (size_t)(bm + r0) * lda + k0 + cv);
        cpa16(&st->Asl[r0 + 64][cv], Alb + (size_t)(bm + r0 + 64) * lda + k0 + cv);
        cpa16(&st->Bsh[r0][cv],      Bhb + (size_t)(bn + r0) * ldb + k0 + cv);
        cpa16(&st->Bsh[r0 + 64][cv], Bhb + (size_t)(bn + r0 + 64) * ldb + k0 + cv);
        cpa16(&st->Bsl[r0][cv],      Blb + (size_t)(bn + r0) * ldb + k0 + cv);
        cpa16(&st->Bsl[r0 + 64][cv], Blb + (size_t)(bn + r0 + 64) * ldb + k0 + cv);
    };

    load_stage(&sm->st[0], 0);
    CPA_COMMIT();

    for (int t = 0; t < T; t++) {
        if (t + 1 < T) {
            load_stage(&sm->st[(t + 1) & 1], (t + 1) * 32);
            CPA_COMMIT();
            CPA_WAIT(1);
        } else {
            CPA_WAIT(0);
        }
        __syncthreads();
        BmmaStage* st = &sm->st[t & 1];

        #pragma unroll
        for (int kk = 0; kk < 32; kk += 16) {
            uint32_t bh[4][2], bl[4][2];
            #pragma unroll
            for (int nt = 0; nt < 4; nt++) {
                int n = wn * 32 + nt * 8 + gr;
                bh[nt][0] = *(const uint32_t*)&st->Bsh[n][kk + ct * 2];
                bh[nt][1] = *(const uint32_t*)&st->Bsh[n][kk + ct * 2 + 8];
                bl[nt][0] = *(const uint32_t*)&st->Bsl[n][kk + ct * 2];
                bl[nt][1] = *(const uint32_t*)&st->Bsl[n][kk + ct * 2 + 8];
            }
            #pragma unroll
            for (int mt = 0; mt < 4; mt++) {
                int rA = wm * 64 + mt * 16 + gr;
                uint32_t ah0 = *(const uint32_t*)&st->Ash[rA][kk + ct * 2];
                uint32_t ah1 = *(const uint32_t*)&st->Ash[rA + 8][kk + ct * 2];
                uint32_t ah2 = *(const uint32_t*)&st->Ash[rA][kk + ct * 2 + 8];
                uint32_t ah3 = *(const uint32_t*)&st->Ash[rA + 8][kk + ct * 2 + 8];
                uint32_t al0 = *(const uint32_t*)&st->Asl[rA][kk + ct * 2];
                uint32_t al1 = *(const uint32_t*)&st->Asl[rA + 8][kk + ct * 2];
                uint32_t al2 = *(const uint32_t*)&st->Asl[rA][kk + ct * 2 + 8];
                uint32_t al3 = *(const uint32_t*)&st->Asl[rA + 8][kk + ct * 2 + 8];
                #pragma unroll
                for (int nt = 0; nt < 4; nt++) {
                    MMA_BF16(acc[mt][nt], ah0, ah1, ah2, ah3, bh[nt][0], bh[nt][1]);
                    MMA_BF16(acc[mt][nt], ah0, ah1, ah2, ah3, bl[nt][0], bl[nt][1]);
                    MMA_BF16(acc[mt][nt], al0, al1, al2, al3, bh[nt][0], bh[nt][1]);
                }
            }
        }
        __syncthreads();
    }

    if (MODE != 5 && MODE != 4) {
        #pragma unroll
        for (int mt = 0; mt < 4; mt++) {
            int row = bm + wm * 64 + mt * 16 + gr;
            #pragma unroll
            for (int nt = 0; nt < 4; nt++) {
                int col = bn + wn * 32 + nt * 8 + ct * 2;
                float v0 = acc[mt][nt][0], v1 = acc[mt][nt][1];
                float v2 = acc[mt][nt][2], v3 = acc[mt][nt][3];
                if (MODE == 1) {
                    float b0 = biasb[col], b1 = biasb[col + 1];
                    v0 += b0; v1 += b1; v2 += b0; v3 += b1;
                } else if (MODE == 3) {
                    float sr0 = bias[row], sr1 = bias[row + 8];
                    float sc0 = bias[col], sc1 = bias[col + 1];
                    v0 = sr0 + sc0 - 2.f * v0;
                    v1 = sr0 + sc1 - 2.f * v1;
                    v2 = sr1 + sc0 - 2.f * v2;
                    v3 = sr1 + sc1 - 2.f * v3;
                }
                *(float2*)(Cb + (size_t)row * ldc + col) = make_float2(v0, v1);
                *(float2*)(Cb + (size_t)(row + 8) * ldc + col) = make_float2(v2, v3);
            }
        }
    }

    if (MODE == 4) {
        float a1c[4][2], a2c[4][2];
        #pragma unroll
        for (int nt = 0; nt < 4; nt++) {
            int col = wn * 32 + nt * 8 + ct * 2;
            a1c[nt][0] = biasb[col];      a1c[nt][1] = biasb[col + 1];
            a2c[nt][0] = biasb[Dd + col]; a2c[nt][1] = biasb[Dd + col + 1];
        }
        float p1[8], p2[8];
        #pragma unroll
        for (int ri = 0; ri < 8; ri++) {
            int mt = ri >> 1, h2 = ri & 1;
            float s1 = 0.f, s2 = 0.f;
            #pragma unroll
            for (int nt = 0; nt < 4; nt++) {
                float v0 = acc[mt][nt][h2 * 2 + 0], v1 = acc[mt][nt][h2 * 2 + 1];
                s1 += v0 * a1c[nt][0] + v1 * a1c[nt][1];
                s2 += v0 * a2c[nt][0] + v1 * a2c[nt][1];
            }
            p1[ri] = s1; p2[ri] = s2;
        }
        #pragma unroll
        for (int ri = 0; ri < 8; ri++) {
            p1[ri] += __shfl_xor_sync(0xffffffffu, p1[ri], 1);
            p1[ri] += __shfl_xor_sync(0xffffffffu, p1[ri], 2);
            p2[ri] += __shfl_xor_sync(0xffffffffu, p2[ri], 1);
            p2[ri] += __shfl_xor_sync(0xffffffffu, p2[ri], 2);
        }
        if (ct == 0) {
            #pragma unroll
            for (int ri = 0; ri < 8; ri++) {
                int rl = wm * 64 + (ri >> 1) * 16 + gr + (ri & 1) * 8;
                sm->red1[wn][rl] = p1[ri];
                sm->red2[wn][rl] = p2[ri];
            }
        }
        __syncthreads();
        if (tid < 128) {
            float f1 = sm->red1[0][tid] + sm->red1[1][tid] + sm->red1[2][tid] + sm->red1[3][tid];
            float f2 = sm->red2[0][tid] + sm->red2[1][tid] + sm->red2[2][tid] + sm->red2[3][tid];
            g_f1[(size_t)z * Nn + bm + tid] = f1;
            g_f2[(size_t)z * Nn + bm + tid] = f2;
        }
    }

    if (MODE == 5) {
        #pragma unroll
        for (int mt = 0; mt < 4; mt++)
            #pragma unroll
            for (int nt = 0; nt < 4; nt++) {
                int col = wn * 32 + nt * 8 + ct * 2;
                float b0 = biasb[col], b1 = biasb[col + 1];
                acc[mt][nt][0] += b0; acc[mt][nt][1] += b1;
                acc[mt][nt][2] += b0; acc[mt][nt][3] += b1;
                #pragma unroll
                for (int q = 0; q < 4; q++) {
                    float v = acc[mt][nt][q];
                    acc[mt][nt][q] = (v > 0.f) ? v : expm1f(v);
                }
            }
        float rm[8];
        #pragma unroll
        for (int ri = 0; ri < 8; ri++) {
            int mt = ri >> 1, h2 = ri & 1;
            float m = -FLT_MAX;
            #pragma unroll
            for (int nt = 0; nt < 4; nt++)
                m = fmaxf(m, fmaxf(acc[mt][nt][h2 * 2], acc[mt][nt][h2 * 2 + 1]));
            rm[ri] = m;
        }
        #pragma unroll
        for (int ri = 0; ri < 8; ri++) {
            rm[ri] = fmaxf(rm[ri], __shfl_xor_sync(0xffffffffu, rm[ri], 1));
            rm[ri] = fmaxf(rm[ri], __shfl_xor_sync(0xffffffffu, rm[ri], 2));
        }
        if (ct == 0)
            #pragma unroll
            for (int ri = 0; ri < 8; ri++)
                sm->red1[wn][wm * 64 + (ri >> 1) * 16 + gr + (ri & 1) * 8] = rm[ri];
        __syncthreads();
        if (tid < 128)
            sm->srow[tid] = fmaxf(fmaxf(sm->red1[0][tid], sm->red1[1][tid]),
                                  fmaxf(sm->red1[2][tid], sm->red1[3][tid]));
        __syncthreads();
        float se[8];
        #pragma unroll
        for (int ri = 0; ri < 8; ri++) {
            int mt = ri >> 1, h2 = ri & 1;
            int rl = wm * 64 + mt * 16 + gr + h2 * 8;
            float m = sm->srow[rl];
            float s = 0.f;
            #pragma unroll
            for (int nt = 0; nt < 4; nt++)
                s += expf(acc[mt][nt][h2 * 2] - m) + expf(acc[mt][nt][h2 * 2 + 1] - m);
            se[ri] = s;
        }
        #pragma unroll
        for (int ri = 0; ri < 8; ri++) {
            se[ri] += __shfl_xor_sync(0xffffffffu, se[ri], 1);
            se[ri] += __shfl_xor_sync(0xffffffffu, se[ri], 2);
        }
        __syncthreads();
        if (ct == 0)
            #pragma unroll
            for (int ri = 0; ri < 8; ri++)
                sm->red1[wn][wm * 64 + (ri >> 1) * 16 + gr + (ri & 1) * 8] = se[ri];
        __syncthreads();
        if (tid < 128)
            sm->srow[tid] += logf(sm->red1[0][tid] + sm->red1[1][tid] +
                                  sm->red1[2][tid] + sm->red1[3][tid]);
        __syncthreads();
        #pragma unroll
        for (int mt = 0; mt < 4; mt++) {
            #pragma unroll
            for (int nt = 0; nt < 4; nt++) {
                int col = wn * 32 + nt * 8 + ct * 2;
                int rl0 = wm * 64 + mt * 16 + gr;
                float l0 = sm->srow[rl0], l1 = sm->srow[rl0 + 8];
                *(float2*)(Cb + (size_t)(bm + rl0) * ldc + col) =
                    make_float2(acc[mt][nt][0] - l0, acc[mt][nt][1] - l0);
                *(float2*)(Cb + (size_t)(bm + rl0 + 8) * ldc + col) =
                    make_float2(acc[mt][nt][2] - l1, acc[mt][nt][3] - l1);
            }
        }
    }
}

// ---- mega GEMM: dist (0..255) + f12 (256..447) + rec (448..639) + W2 (640..651) ----
__global__ __launch_bounds__(256, 2) void mega_gemm(
    float* __restrict__ rec, const float* __restrict__ gat_a,
    const float* __restrict__ enc_b)
{
    extern __shared__ char smbuf[];
    BmmaSmem* sm = (BmmaSmem*)smbuf;
    int b = blockIdx.x;
    if (b < 256) {
        bmma_tile<3>(sm, g_lat_h, g_lat_l, g_lat_h, g_lat_l,
                     g_dist, g_sq, nullptr,
                     0, (b >> 4) * 128, (b & 15) * 128, Dd, Dd, Dd, Nn);
    } else if (b < 448) {
        int t = b - 256; int z = t >> 4; int bm = (t & 15) * 128;
        bmma_tile<4>(sm, g_lat_h, g_lat_l,
                     g_gwT_h + (size_t)z * Dd * Dd, g_gwT_l + (size_t)z * Dd * Dd,
                     nullptr, nullptr, gat_a + (size_t)z * 2 * Dd,
                     z, bm, 0, Dd, Dd, Dd, Dd);
    } else if (b < 640) {
        int t = b - 448; int z = t >> 6; int r = t & 63;
        bmma_tile<1>(sm, g_lat_h, g_lat_l,
                     g_encT_h + (size_t)z * VDd * Dd, g_encT_l + (size_t)z * VDd * Dd,
                     rec + (size_t)z * Nn * VDd, nullptr, enc_b + (size_t)z * VDd,
                     z, (r >> 2) * 128, (r & 3) * 128, Dd, Dd, Dd, VDd);
    } else {
        int vh = b - 640;
        bmma_tile<0>(sm,
                     g_gw_h + (size_t)vh * Dd * Dd, g_gw_l + (size_t)vh * Dd * Dd,
                     g_aggT_h + (size_t)vh * Dd, g_aggT_l + (size_t)vh * Dd,
                     g_W2 + (size_t)vh * Dd * Dd, nullptr, nullptr,
                     vh, 0, 0, Dd, Dd, VH * Dd, Dd);
    }
}

// ---------------- semantic partials = mixed @ W2 (split-K) ----------------
__global__ __launch_bounds__(256, 2) void agg_gemm() {
    extern __shared__ char smbuf[];
    BmmaSmem* sm = (BmmaSmem*)smbuf;
    int z = blockIdx.z;
    bmma_tile<0>(sm,
                 g_mix_h + (size_t)z * AGG_KCHUNK, g_mix_l + (size_t)z * AGG_KCHUNK,
                 g_W2T_h + (size_t)z * AGG_KCHUNK, g_W2T_l + (size_t)z * AGG_KCHUNK,
                 g_part + (size_t)z * Nn * Dd, nullptr, nullptr,
                 z, blockIdx.y * 128, 0, AGG_KCHUNK, VH * Dd, VH * Dd, Dd);
}

// ---------------- cls + elu + log_softmax (final output) ----------------
__global__ __launch_bounds__(256, 2) void cls_gemm(float* __restrict__ outp,
                                                   const float* __restrict__ cls_b) {
    extern __shared__ char smbuf[];
    BmmaSmem* sm = (BmmaSmem*)smbuf;
    bmma_tile<5>(sm, g_sem_h, g_sem_l, g_clsT_h, g_clsT_l,
                 outp, nullptr, cls_b,
                 0, blockIdx.y * 128, 0, Dd, Dd, Dd, Dd);
}

// ---- fused knn + attn (blocks 0..1023) + W2 transpose/split (1024..1215) ----
__global__ __launch_bounds__(256) void knn_attn_kernel(const float* __restrict__ fm,
                                                       const float* __restrict__ latent) {
    if (blockIdx.x >= Nn / 2) {
        int t = blockIdx.x - Nn / 2;
        trans_tile(g_W2, VH * Dd, Dd, g_W2T_h, g_W2T_l, t >> 2, t & 3, threadIdx.x);
        return;
    }
    __shared__ float sval[8][Kk];
    __shared__ int   sidx[8][Kk];
    __shared__ int   sknn[2][Kk];
    int tid = threadIdx.x;
    int wid = tid >> 5, lane = tid & 31;
    int row = blockIdx.x * 2 + (wid >> 2);
    int quarter = wid & 3;
    const float* dr = g_dist + (size_t)row * Nn + quarter * 512;

    float4 v4[4];
    #pragma unroll
    for (int t = 0; t < 4; t++)
        v4[t] = *(const float4*)(dr + t * 128 + lane * 4);

    float val[Kk];
    int   idx[Kk];
    #pragma unroll
    for (int p = 0; p < Kk; p++) { val[p] = FLT_MAX; idx[p] = 0x7fffffff; }

    #pragma unroll
    for (int t = 0; t < 4; t++) {
        float c[4] = {v4[t].x, v4[t].y, v4[t].z, v4[t].w};
        #pragma unroll
        for (int q = 0; q < 4; q++) {
            float d = c[q];
            if (d < val[Kk - 1]) {
                int gj = quarter * 512 + t * 128 + lane * 4 + q;
                #pragma unroll
                for (int p = Kk - 1; p >= 1; p--) {
                    if (d < val[p]) {
                        bool sh = d < val[p - 1];
                        val[p] = sh ? val[p - 1] : d;
                        idx[p] = sh ? idx[p - 1] : gj;
                    }
                }
                if (d < val[0]) { val[0] = d; idx[0] = gj; }
            }
        }
    }

    #pragma unroll 1
    for (int r = 0; r < Kk; r++) {
        float bv = val[0]; int bi = idx[0];
        #pragma unroll
        for (int o = 16; o; o >>= 1) {
            float ov = __shfl_xor_sync(0xffffffffu, bv, o);
            int   oi = __shfl_xor_sync(0xffffffffu, bi, o);
            if (ov < bv || (ov == bv && oi < bi)) { bv = ov; bi = oi; }
        }
        if (lane == 0) { sval[wid][r] = bv; sidx[wid][r] = bi; }
        if (val[0] == bv && idx[0] == bi) {
            #pragma unroll
            for (int p = 0; p < Kk - 1; p++) { val[p] = val[p + 1]; idx[p] = idx[p + 1]; }
            val[Kk - 1] = FLT_MAX; idx[Kk - 1] = 0x7fffffff;
        }
    }
    __syncthreads();

    if ((wid & 3) == 0) {
        int wbase = wid;
        float a = FLT_MAX; int ai = 0x7fffffff;
        float b = FLT_MAX; int bi = 0x7fffffff;
        if (lane < 40) { a = sval[wbase + lane / Kk][lane % Kk]; ai = sidx[wbase + lane / Kk][lane % Kk]; }
        int l2 = lane + 32;
        if (l2 < 40) { b = sval[wbase + l2 / Kk][l2 % Kk]; bi = sidx[wbase + l2 / Kk][l2 % Kk]; }
        #pragma unroll 1
        for (int r = 0; r < Kk; r++) {
            bool useB = (b < a) || (b == a && bi < ai);
            float cv = useB ? b : a;
            int   ci = useB ? bi : ai;
            float mv = cv; int mi = ci;
            #pragma unroll
            for (int o = 16; o; o >>= 1) {
                float ov = __shfl_xor_sync(0xffffffffu, mv, o);
                int   oi = __shfl_xor_sync(0xffffffffu, mi, o);
                if (ov < mv || (ov == mv && oi < mi)) { mv = ov; mi = oi; }
            }
            if (lane == 0) sknn[wid >> 2][r] = mi;
            if (cv == mv && ci == mi) {
                if (useB) { b = FLT_MAX; bi = 0x7fffffff; }
                else      { a = FLT_MAX; ai = 0x7fffffff; }
            }
        }
    }
    __syncthreads();

    // ---- attention phase: 24 tasks (2 rows x 12 vh), 3 per warp ----
    #pragma unroll 1
    for (int tt = wid; tt < 2 * VH; tt += 8) {
        int rl = tt / VH;
        int vh = tt - rl * VH;
        int i = blockIdx.x * 2 + rl;
        int v = vh >> 2;

        int nb = -1;
        bool valid = false;
        if (lane < Kk) {
            nb = sknn[rl][lane];
            valid = (nb == i) || (fm[(size_t)i * Vv + v] > 0.f && fm[(size_t)nb * Vv + v] > 0.f);
        }
        unsigned hasSelf = __ballot_sync(0xffffffffu, lane < Kk && nb == i);
        if (hasSelf == 0 && lane == Kk) { nb = i; valid = true; }

        float e = -FLT_MAX;
        if (valid) {
            float x = g_f1[vh * Nn + i] + g_f2[(size_t)vh * Nn + nb];
            e = (x >= 0.f) ? x : LRELU_ALPHA * x;
        }
        float m = e;
        #pragma unroll
        for (int o = 16; o; o >>= 1) m = fmaxf(m, __shfl_xor_sync(0xffffffffu, m, o));
        float wt = valid ? expf(e - m) : 0.f;
        float s = wt;
        #pragma unroll
        for (int o = 16; o; o >>= 1) s += __shfl_xor_sync(0xffffffffu, s, o);
        float att = wt / s;

        float av[Kk + 1];
        int   nj[Kk + 1];
        #pragma unroll
        for (int j = 0; j <= Kk; j++) {
            av[j] = __shfl_sync(0xffffffffu, att, j);
            int n = __shfl_sync(0xffffffffu, nb, j);
            nj[j] = (av[j] != 0.f) ? n : i;
        }
        float4 wv[Kk + 1];
        #pragma unroll
        for (int j = 0; j <= Kk; j++)
            wv[j] = *(const float4*)(latent + (size_t)nj[j] * Dd + lane * 4);

        float acc0 = 0.f, acc1 = 0.f, acc2 = 0.f, acc3 = 0.f;
        #pragma unroll
        for (int j = 0; j <= Kk; j++) {
            acc0 = fmaf(av[j], wv[j].x, acc0);
            acc1 = fmaf(av[j], wv[j].y, acc1);
            acc2 = fmaf(av[j], wv[j].z, acc2);
            acc3 = fmaf(av[j], wv[j].w, acc3);
        }
        union { __nv_bfloat16 b[4]; uint2 u; } H, L;
        float c4[4] = {acc0, acc1, acc2, acc3};
        #pragma unroll
        for (int q = 0; q < 4; q++) {
            H.b[q] = __float2bfloat16(c4[q]);
            L.b[q] = __float2bfloat16(c4[q] - __bfloat162float(H.b[q]));
        }
        size_t dst = (size_t)i * (VH * Dd) + (size_t)vh * Dd + lane * 4;
        *(uint2*)(g_mix_h + dst) = H.u;
        *(uint2*)(g_mix_l + dst) = L.u;
    }
}

// ---------------- split-K reduce for semantic + bias -> sem fp32 + bf16 split ----------------
__global__ void agg_reduce_kernel(const float* __restrict__ bias, float* __restrict__ sem) {
    int i = blockIdx.x * blockDim.x + threadIdx.x;
    if (i >= Nn * Dd) return;
    float s = 0.f;
    #pragma unroll
    for (int p = 0; p < AGG_SPLITS; p++) s += g_part[(size_t)p * Nn * Dd + i];
    s += bias[i & (Dd - 1)];
    sem[i] = s;
    __nv_bfloat16 h = __float2bfloat16(s);
    g_sem_h[i] = h;
    g_sem_l[i] = __float2bfloat16(s - __bfloat162float(h));
}

// ---------------- launch ----------------
extern "C" void kernel_launch(void* const* d_in, const int* in_sizes, int n_in,
                              void* d_out, int out_size) {
    const float* fm     = (const float*)d_in[0];
    const float* latent = (const float*)d_in[1];
    const float* enc_W  = (const float*)d_in[2];
    const float* enc_b  = (const float*)d_in[3];
    const float* gat_W  = (const float*)d_in[4];
    const float* gat_a  = (const float*)d_in[5];
    const float* agg_W  = (const float*)d_in[6];
    const float* agg_b  = (const float*)d_in[7];
    const float* cls_W  = (const float*)d_in[8];
    const float* cls_b  = (const float*)d_in[9];

    float* out  = (float*)d_out;
    float* rec  = out;                                   // [V,N,VD]
    float* outp = out + (size_t)Vv * Nn * VDd;           // [N,D]
    float* sem  = outp + (size_t)Nn * Dd;                // [N,D]

    static bool attr_set = false;
    if (!attr_set) {
        cudaFuncSetAttribute(mega_gemm, cudaFuncAttributeMaxDynamicSharedMemorySize,
                             (int)BMMA_SMEM_BYTES);
        cudaFuncSetAttribute(agg_gemm, cudaFuncAttributeMaxDynamicSharedMemorySize,
                             (int)BMMA_SMEM_BYTES);
        cudaFuncSetAttribute(cls_gemm, cudaFuncAttributeMaxDynamicSharedMemorySize,
                             (int)BMMA_SMEM_BYTES);
        attr_set = true;
    }

    // 1. prep: transposes/splits + latent + plain gat_W split
    prep_all<<<1616, 256>>>(gat_W, enc_W, agg_W, cls_W, latent);
    // 2. mega GEMM: dist + f12 + rec + W2 (cp.async double-buffered)
    mega_gemm<<<652, 256, BMMA_SMEM_BYTES>>>(rec, gat_a, enc_b);
    // 3. fused knn + attention (smem knn handoff) + W2 transpose
    knn_attn_kernel<<<Nn / 2 + 192, 256>>>(fm, latent);
    // 4. semantic partials = mixed @ W2 (split-K)
    agg_gemm<<<dim3(1, Nn / 128, AGG_SPLITS), 256, BMMA_SMEM_BYTES>>>();
    // 5. reduce partials + bias -> semantic (fp32 out + bf16 split)
    agg_reduce_kernel<<<(Nn * Dd) / 256, 256>>>(agg_b, sem);
    // 6. output = log_softmax(elu(sem @ cls_W + cls_b))
    cls_gemm<<<dim3(1, Nn / 128, 1), 256, BMMA_SMEM_BYTES>>>(outp, cls_b);
}